// round 12
// baseline (speedup 1.0000x reference)
#include <cuda_runtime.h>
#include <cuda_fp16.h>
#include <cstdint>

// FIR bandpass as banded-Toeplitz GEMM on mma.sync — fp16, deep-M, cp.async.
// R9: 128-sample chunks (half the syncs), single-pass epilogue, fast build_ext.
//
// out[t] = sum_j g[j] * xv[t-206+j],  g[j] = h[412-j]
// D[i,n] = sum_k A[i,k] * B[n,k],  A[i,k] = g[k-i]  (banded: 0 <= k-i <= 412)

#define T_LEN    30000
#define NROWS    2048
#define HALF     206
#define NKB      34            // k16 blocks (K = 544)
#define NCHUNK   5             // chunks of 128 samples (covers kb 0..39; >=34 self-skip)
#define DMAX     26
#define NTHREADS 256
#define NT_I0    235           // ceil(30000/128)
#define EXT_STRIDE 30720       // halves per row (30412 used, padded, 16B-aligned)

#define AS_STRIDE 912          // 448 fp16 + 16B pad
#define BS_STRIDE 272          // 128 fp16 (256B) + 16B pad
#define OFF_AS   0             // 16 * 912 = 14592
#define OFF_B0   14592         // 128 * 272 = 34816
#define OFF_B1   49408
#define SMEM_REQ 84224         // epilogue staging 128*136*4 = 69632 fits

// reflect-extended fp16 signal: ext[row][e] = xv[row][e - 206]
__device__ __align__(16) __half g_ext[(size_t)NROWS * EXT_STRIDE];
__device__ __align__(16) char g_As[16 * AS_STRIDE];

__device__ __forceinline__ uint32_t smem_u32(const void* p) {
    return (uint32_t)__cvta_generic_to_shared(p);
}
__device__ __forceinline__ void ldx4(uint32_t r[4], uint32_t addr) {
    asm volatile("ldmatrix.sync.aligned.m8n8.x4.shared.b16 {%0,%1,%2,%3}, [%4];"
                 : "=r"(r[0]), "=r"(r[1]), "=r"(r[2]), "=r"(r[3]) : "r"(addr));
}
__device__ __forceinline__ void mma_f16(float c[4], const uint32_t a[4],
                                        const uint32_t b0, const uint32_t b1) {
    asm volatile(
        "mma.sync.aligned.m16n8k16.row.col.f32.f16.f16.f32 "
        "{%0,%1,%2,%3}, {%4,%5,%6,%7}, {%8,%9}, {%0,%1,%2,%3};"
        : "+f"(c[0]), "+f"(c[1]), "+f"(c[2]), "+f"(c[3])
        : "r"(a[0]), "r"(a[1]), "r"(a[2]), "r"(a[3]), "r"(b0), "r"(b1));
}
#define CP_ASYNC16(dst, src) \
    asm volatile("cp.async.cg.shared.global [%0], [%1], 16;" :: "r"(dst), "l"(src))
#define CP_COMMIT() asm volatile("cp.async.commit_group;" ::: "memory")
#define CP_WAIT(n)  asm volatile("cp.async.wait_group %0;" :: "n"(n) : "memory")

// ---------- pre-kernel 1: reflect-extended fp16 signal (16B stores) ----------
__global__ void build_ext(const float* __restrict__ x) {
    const int row = blockIdx.x;
    const float* __restrict__ xr = x + (size_t)row * T_LEN;
    __half* __restrict__ er = g_ext + (size_t)row * EXT_STRIDE;
    const float x0 = xr[0], xl = xr[T_LEN - 1];
    for (int e0 = 8 * threadIdx.x; e0 < EXT_STRIDE; e0 += 8 * 256) {
        const int m0 = e0 - HALF;               // even (HALF even, e0 mult of 8)
        __half v[8];
        if (m0 >= 0 && m0 + 8 <= T_LEN) {
#pragma unroll
            for (int u = 0; u < 4; ++u) {
                const float2 f = *reinterpret_cast<const float2*>(xr + m0 + 2 * u);
                v[2 * u]     = __float2half_rn(f.x);
                v[2 * u + 1] = __float2half_rn(f.y);
            }
        } else {
#pragma unroll
            for (int u = 0; u < 8; ++u) {
                const int m = m0 + u;
                float t;
                if (m < 0)           t = 2.0f * x0 - xr[-m];
                else if (m >= T_LEN) t = 2.0f * xl - xr[2 * T_LEN - 2 - m];
                else                 t = xr[m];
                v[u] = __float2half_rn(t);
            }
        }
        *reinterpret_cast<uint4*>(er + e0) = *reinterpret_cast<const uint4*>(v);
    }
}

// ---------- pre-kernel 2: Toeplitz strip ----------
__global__ void build_as(const float* __restrict__ hcoef) {
    for (int idx = threadIdx.x; idx < 16 * 448; idx += 256) {
        const int r  = idx / 448;
        const int kq = idx - r * 448;
        const int j  = kq - r;
        const float gv = (j >= 0 && j <= 412) ? hcoef[412 - j] : 0.0f;
        *reinterpret_cast<__half*>(g_As + r * AS_STRIDE + 2 * kq) = __float2half_rn(gv);
    }
}

// ---------- main kernel ----------
__global__ void __launch_bounds__(NTHREADS, 2)
fir_mma(float* __restrict__ out) {
    extern __shared__ char smem[];
    const uint32_t sb = smem_u32(smem);
    const int tid  = threadIdx.x;
    const int wid  = tid >> 5;
    const int lane = tid & 31;
    const int wm   = wid >> 2;           // 0..1 : m-blocks 4wm+e
    const int wn   = wid & 3;            // 0..3 : n cols [32wn, 32wn+32)
    const int i0   = blockIdx.x;
    const int r0   = blockIdx.y * 128;

    // ---- copy Toeplitz strip to smem ----
    {
        const uint4* src = reinterpret_cast<const uint4*>(g_As);
        uint4* dst = reinterpret_cast<uint4*>(smem + OFF_AS);
        for (int i = tid; i < (16 * AS_STRIDE) / 16; i += NTHREADS) dst[i] = src[i];
    }

    // ---- producer: thread -> (row, 128B segment), pure cp.async ----
    const int prow = tid >> 1;
    const int pseg = tid & 1;
    const __half* psrc = g_ext + (size_t)(r0 + prow) * EXT_STRIDE
                         + i0 * 128 + pseg * 64;
    const uint32_t pdst = sb + (uint32_t)(prow * BS_STRIDE + pseg * 128);

    // ---- consumer ldmatrix addresses ----
    const uint32_t as_base = sb + OFF_AS +
        (uint32_t)((lane & 15) * AS_STRIDE + ((lane >> 4) & 1) * 16);
    const uint32_t b_off = (uint32_t)((32 * wn + 8 * ((lane >> 4) & 1) + (lane & 7)) * BS_STRIDE
                                      + 16 * ((lane >> 3) & 1));

    float acc[4][4][4];
#pragma unroll
    for (int e = 0; e < 4; ++e)
#pragma unroll
        for (int nb = 0; nb < 4; ++nb)
#pragma unroll
            for (int q = 0; q < 4; ++q) acc[e][nb][q] = 0.0f;

    uint32_t af[4][4];                   // A-fragment rotation ring

    // prologue: chunk 0 in flight
    {
        const uint32_t d = pdst + OFF_B0;
#pragma unroll
        for (int q = 0; q < 8; ++q) CP_ASYNC16(d + 16 * q, psrc + 8 * q);
        CP_COMMIT();
    }

    for (int c = 0; c < NCHUNK; ++c) {
        if (c + 1 < NCHUNK) {
            const __half* s = psrc + 128 * (c + 1);
            const uint32_t d = pdst + (((c + 1) & 1) ? OFF_B1 : OFF_B0);
#pragma unroll
            for (int q = 0; q < 8; ++q) CP_ASYNC16(d + 16 * q, s + 8 * q);
            CP_COMMIT();
            CP_WAIT(1);
        } else {
            CP_WAIT(0);
        }
        __syncthreads();

        const uint32_t bbuf = sb + ((c & 1) ? OFF_B1 : OFF_B0) + b_off;
        const int base = 8 * c - 4 * wm;

#pragma unroll
        for (int j = 0; j < 8; ++j) {
            const int dnew = base + j;                     // diag for block e=0
            if ((unsigned)dnew <= (unsigned)DMAX)
                ldx4(af[j & 3], as_base + (dnew << 5));

            if (dnew >= 0 && dnew <= DMAX + 3) {           // some block valid
#pragma unroll
                for (int nbp = 0; nbp < 2; ++nbp) {
                    uint32_t bh[4];
                    ldx4(bh, bbuf + (uint32_t)(nbp * 16 * BS_STRIDE + 32 * j));
#pragma unroll
                    for (int s = 0; s < 2; ++s) {
                        const int nb = 2 * nbp + s;
#pragma unroll
                        for (int e = 0; e < 4; ++e)
                            if ((unsigned)(dnew - e) <= (unsigned)DMAX)
                                mma_f16(acc[e][nb], af[(j - e) & 3],
                                        bh[2 * s], bh[2 * s + 1]);
                    }
                }
            }
        }
        __syncthreads();
    }

    // ---- epilogue: single-pass smem transpose -> coalesced stores ----
    float* S = reinterpret_cast<float*>(smem);    // S[n][t], stride 136 floats
#pragma unroll
    for (int e = 0; e < 4; ++e)
#pragma unroll
        for (int nb = 0; nb < 4; ++nb) {
            const int tl = 64 * wm + 16 * e + (lane >> 2);
            const int nl = 32 * wn + 8 * nb + 2 * (lane & 3);
            S[nl * 136 + tl]           = acc[e][nb][0];
            S[(nl + 1) * 136 + tl]     = acc[e][nb][1];
            S[nl * 136 + tl + 8]       = acc[e][nb][2];
            S[(nl + 1) * 136 + tl + 8] = acc[e][nb][3];
        }
    __syncthreads();

    const int tg = i0 * 128 + 4 * lane;
    if (tg < T_LEN) {
#pragma unroll
        for (int rr = 0; rr < 16; ++rr) {
            const int n = wid * 16 + rr;
            const float4 v = *reinterpret_cast<const float4*>(&S[n * 136 + 4 * lane]);
            *reinterpret_cast<float4*>(&out[(size_t)(r0 + n) * T_LEN + tg]) = v;
        }
    }
}

extern "C" void kernel_launch(void* const* d_in, const int* in_sizes, int n_in,
                              void* d_out, int out_size) {
    const float* x = (const float*)d_in[0];   // (32, 64, 30000) f32
    const float* h = (const float*)d_in[1];   // (413,) f32
    float* out = (float*)d_out;

    cudaFuncSetAttribute(fir_mma,
                         cudaFuncAttributeMaxDynamicSharedMemorySize, SMEM_REQ);

    build_ext<<<NROWS, 256>>>(x);
    build_as<<<1, 256>>>(h);

    dim3 grid(NT_I0, NROWS / 128);
    fir_mma<<<grid, NTHREADS, SMEM_REQ>>>(out);
}

// round 13
// speedup vs baseline: 1.1344x; 1.1344x over previous
#include <cuda_runtime.h>
#include <cuda_fp16.h>
#include <cstdint>

// FIR bandpass as banded-Toeplitz GEMM on mma.sync — fp16, deep-M, cp.async.
// R13 = R8 mainloop (64-sample chunks — R9's 128 regressed) + R9 fast build_ext
//       + single-pass epilogue (full 128x136 staging tile).
//
// out[t] = sum_j g[j] * xv[t-206+j],  g[j] = h[412-j]
// D[i,n] = sum_k A[i,k] * B[n,k],  A[i,k] = g[k-i]  (banded: 0 <= k-i <= 412)

#define T_LEN    30000
#define NROWS    2048
#define HALF     206
#define NKB      34            // k16 blocks (K = 544)
#define NCHUNK   9             // chunks of 64 samples
#define DMAX     26
#define NTHREADS 256
#define NT_I0    235           // ceil(30000/128)
#define EXT_STRIDE 30720       // halves per row (30412 used, padded, 16B-aligned)

#define AS_STRIDE 912          // 448 fp16 + 16B pad
#define BS_STRIDE 144          // 64 fp16 + 16B pad
#define OFF_AS   0             // 16 * 912 = 14592
#define OFF_B0   14592         // 128 * 144 = 18432
#define OFF_B1   33024
#define SMEM_REQ 69632         // epilogue staging 128*136*4 dominates

// reflect-extended fp16 signal: ext[row][e] = xv[row][e - 206]
__device__ __align__(16) __half g_ext[(size_t)NROWS * EXT_STRIDE];
__device__ __align__(16) char g_As[16 * AS_STRIDE];

__device__ __forceinline__ uint32_t smem_u32(const void* p) {
    return (uint32_t)__cvta_generic_to_shared(p);
}
__device__ __forceinline__ void ldx4(uint32_t r[4], uint32_t addr) {
    asm volatile("ldmatrix.sync.aligned.m8n8.x4.shared.b16 {%0,%1,%2,%3}, [%4];"
                 : "=r"(r[0]), "=r"(r[1]), "=r"(r[2]), "=r"(r[3]) : "r"(addr));
}
__device__ __forceinline__ void mma_f16(float c[4], const uint32_t a[4],
                                        const uint32_t b0, const uint32_t b1) {
    asm volatile(
        "mma.sync.aligned.m16n8k16.row.col.f32.f16.f16.f32 "
        "{%0,%1,%2,%3}, {%4,%5,%6,%7}, {%8,%9}, {%0,%1,%2,%3};"
        : "+f"(c[0]), "+f"(c[1]), "+f"(c[2]), "+f"(c[3])
        : "r"(a[0]), "r"(a[1]), "r"(a[2]), "r"(a[3]), "r"(b0), "r"(b1));
}
#define CP_ASYNC16(dst, src) \
    asm volatile("cp.async.cg.shared.global [%0], [%1], 16;" :: "r"(dst), "l"(src))
#define CP_COMMIT() asm volatile("cp.async.commit_group;" ::: "memory")
#define CP_WAIT(n)  asm volatile("cp.async.wait_group %0;" :: "n"(n) : "memory")

// ---------- pre-kernel 1: reflect-extended fp16 signal (16B stores) ----------
__global__ void build_ext(const float* __restrict__ x) {
    const int row = blockIdx.x;
    const float* __restrict__ xr = x + (size_t)row * T_LEN;
    __half* __restrict__ er = g_ext + (size_t)row * EXT_STRIDE;
    const float x0 = xr[0], xl = xr[T_LEN - 1];
    for (int e0 = 8 * threadIdx.x; e0 < EXT_STRIDE; e0 += 8 * 256) {
        const int m0 = e0 - HALF;               // even
        __half v[8];
        if (m0 >= 0 && m0 + 8 <= T_LEN) {
#pragma unroll
            for (int u = 0; u < 4; ++u) {
                const float2 f = *reinterpret_cast<const float2*>(xr + m0 + 2 * u);
                v[2 * u]     = __float2half_rn(f.x);
                v[2 * u + 1] = __float2half_rn(f.y);
            }
        } else {
#pragma unroll
            for (int u = 0; u < 8; ++u) {
                const int m = m0 + u;
                float t;
                if (m < 0)           t = 2.0f * x0 - xr[-m];
                else if (m >= T_LEN) t = 2.0f * xl - xr[2 * T_LEN - 2 - m];
                else                 t = xr[m];
                v[u] = __float2half_rn(t);
            }
        }
        *reinterpret_cast<uint4*>(er + e0) = *reinterpret_cast<const uint4*>(v);
    }
}

// ---------- pre-kernel 2: Toeplitz strip ----------
__global__ void build_as(const float* __restrict__ hcoef) {
    for (int idx = threadIdx.x; idx < 16 * 448; idx += 256) {
        const int r  = idx / 448;
        const int kq = idx - r * 448;
        const int j  = kq - r;
        const float gv = (j >= 0 && j <= 412) ? hcoef[412 - j] : 0.0f;
        *reinterpret_cast<__half*>(g_As + r * AS_STRIDE + 2 * kq) = __float2half_rn(gv);
    }
}

// ---------- main kernel ----------
__global__ void __launch_bounds__(NTHREADS, 2)
fir_mma(float* __restrict__ out) {
    extern __shared__ char smem[];
    const uint32_t sb = smem_u32(smem);
    const int tid  = threadIdx.x;
    const int wid  = tid >> 5;
    const int lane = tid & 31;
    const int wm   = wid >> 2;           // 0..1 : m-blocks 4wm+e
    const int wn   = wid & 3;            // 0..3 : n cols [32wn, 32wn+32)
    const int i0   = blockIdx.x;
    const int r0   = blockIdx.y * 128;

    // ---- copy Toeplitz strip to smem ----
    {
        const uint4* src = reinterpret_cast<const uint4*>(g_As);
        uint4* dst = reinterpret_cast<uint4*>(smem + OFF_AS);
        for (int i = tid; i < (16 * AS_STRIDE) / 16; i += NTHREADS) dst[i] = src[i];
    }

    // ---- producer: thread -> (row, 32-sample segment), pure cp.async ----
    const int prow = tid >> 1;
    const int pseg = tid & 1;
    const __half* psrc = g_ext + (size_t)(r0 + prow) * EXT_STRIDE
                         + i0 * 128 + pseg * 32;
    const uint32_t pdst = sb + (uint32_t)(prow * BS_STRIDE + pseg * 64);

    // ---- consumer ldmatrix addresses ----
    const uint32_t as_base = sb + OFF_AS +
        (uint32_t)((lane & 15) * AS_STRIDE + ((lane >> 4) & 1) * 16);
    const uint32_t b_off = (uint32_t)((32 * wn + 8 * ((lane >> 4) & 1) + (lane & 7)) * BS_STRIDE
                                      + 16 * ((lane >> 3) & 1));

    float acc[4][4][4];
#pragma unroll
    for (int e = 0; e < 4; ++e)
#pragma unroll
        for (int nb = 0; nb < 4; ++nb)
#pragma unroll
            for (int q = 0; q < 4; ++q) acc[e][nb][q] = 0.0f;

    uint32_t af[4][4];                   // A-fragment rotation ring

    // prologue: chunk 0 in flight
    {
        const uint32_t d = pdst + OFF_B0;
#pragma unroll
        for (int q = 0; q < 4; ++q) CP_ASYNC16(d + 16 * q, psrc + 8 * q);
        CP_COMMIT();
    }

    for (int c = 0; c < NCHUNK; ++c) {
        if (c + 1 < NCHUNK) {
            const __half* s = psrc + 64 * (c + 1);
            const uint32_t d = pdst + (((c + 1) & 1) ? OFF_B1 : OFF_B0);
#pragma unroll
            for (int q = 0; q < 4; ++q) CP_ASYNC16(d + 16 * q, s + 8 * q);
            CP_COMMIT();
            CP_WAIT(1);                  // chunk c complete (c+1 may be pending)
        } else {
            CP_WAIT(0);
        }
        __syncthreads();

        const uint32_t bbuf = sb + ((c & 1) ? OFF_B1 : OFF_B0) + b_off;
        const int base = 4 * (c - wm);

#pragma unroll
        for (int j = 0; j < 4; ++j) {
            const int dnew = base + j;                     // diag for block e=0
            if ((unsigned)dnew <= (unsigned)DMAX)
                ldx4(af[j & 3], as_base + (dnew << 5));

            if (dnew >= 0 && dnew <= DMAX + 3) {           // some block valid
#pragma unroll
                for (int nbp = 0; nbp < 2; ++nbp) {
                    uint32_t bh[4];
                    ldx4(bh, bbuf + (uint32_t)(nbp * 16 * BS_STRIDE + 32 * j));
#pragma unroll
                    for (int s = 0; s < 2; ++s) {
                        const int nb = 2 * nbp + s;
#pragma unroll
                        for (int e = 0; e < 4; ++e)
                            if ((unsigned)(dnew - e) <= (unsigned)DMAX)
                                mma_f16(acc[e][nb], af[(j - e) & 3],
                                        bh[2 * s], bh[2 * s + 1]);
                    }
                }
            }
        }
        __syncthreads();
    }

    // ---- epilogue: single-pass smem transpose -> coalesced stores ----
    float* S = reinterpret_cast<float*>(smem);    // S[n][t], stride 136 floats
#pragma unroll
    for (int e = 0; e < 4; ++e)
#pragma unroll
        for (int nb = 0; nb < 4; ++nb) {
            const int tl = 64 * wm + 16 * e + (lane >> 2);
            const int nl = 32 * wn + 8 * nb + 2 * (lane & 3);
            S[nl * 136 + tl]           = acc[e][nb][0];
            S[(nl + 1) * 136 + tl]     = acc[e][nb][1];
            S[nl * 136 + tl + 8]       = acc[e][nb][2];
            S[(nl + 1) * 136 + tl + 8] = acc[e][nb][3];
        }
    __syncthreads();

    const int tg = i0 * 128 + 4 * lane;
    if (tg < T_LEN) {
#pragma unroll
        for (int rr = 0; rr < 16; ++rr) {
            const int n = wid * 16 + rr;
            const float4 v = *reinterpret_cast<const float4*>(&S[n * 136 + 4 * lane]);
            *reinterpret_cast<float4*>(&out[(size_t)(r0 + n) * T_LEN + tg]) = v;
        }
    }
}

extern "C" void kernel_launch(void* const* d_in, const int* in_sizes, int n_in,
                              void* d_out, int out_size) {
    const float* x = (const float*)d_in[0];   // (32, 64, 30000) f32
    const float* h = (const float*)d_in[1];   // (413,) f32
    float* out = (float*)d_out;

    cudaFuncSetAttribute(fir_mma,
                         cudaFuncAttributeMaxDynamicSharedMemorySize, SMEM_REQ);

    build_ext<<<NROWS, 256>>>(x);
    build_as<<<1, 256>>>(h);

    dim3 grid(NT_I0, NROWS / 128);
    fir_mma<<<grid, NTHREADS, SMEM_REQ>>>(out);
}

// round 14
// speedup vs baseline: 1.4084x; 1.2415x over previous
#include <cuda_runtime.h>
#include <cuda_fp16.h>
#include <cstdint>

// FIR bandpass as banded-Toeplitz GEMM on mma.sync — fp16, 8-deep-M warps.
// R14: warp layout 1x8 (all 8 m-blocks per warp, 16 rows per warp).
//      Per kb: 1 A-ldx4 + 1 B-ldx4 serve up to 16 MMAs (LDSM/warp 102 -> 70).
//      Full compile-time unroll: ring slots & band predicates constant-fold.
//
// out[t] = sum_j g[j] * xv[t-206+j],  g[j] = h[412-j]
// D[i,n] = sum_k A[i,k] * B[n,k],  A[i,k] = g[k-i]  (banded: 0 <= k-i <= 412)

#define T_LEN    30000
#define NROWS    2048
#define HALF     206
#define NCHUNK   9             // chunks of 64 samples (kb = 0..35; kb>33 folds away)
#define DMAX     26
#define NTHREADS 256
#define NT_I0    235           // ceil(30000/128)
#define EXT_STRIDE 30720       // halves per row (30412 used, padded, 16B-aligned)

#define AS_STRIDE 912          // 448 fp16 + 16B pad  (228 words ≡ 4 mod 32)
#define BS_STRIDE 144          // 64 fp16 + 16B pad   (36 words ≡ 4 mod 32)
#define OFF_AS   0             // 16 * 912 = 14592
#define OFF_B0   14592         // 128 * 144 = 18432
#define OFF_B1   33024
#define SMEM_REQ 69632         // epilogue staging 128*136*4 dominates

// reflect-extended fp16 signal: ext[row][e] = xv[row][e - 206]
__device__ __align__(16) __half g_ext[(size_t)NROWS * EXT_STRIDE];
__device__ __align__(16) char g_As[16 * AS_STRIDE];

__device__ __forceinline__ uint32_t smem_u32(const void* p) {
    return (uint32_t)__cvta_generic_to_shared(p);
}
__device__ __forceinline__ void ldx4(uint32_t r[4], uint32_t addr) {
    asm volatile("ldmatrix.sync.aligned.m8n8.x4.shared.b16 {%0,%1,%2,%3}, [%4];"
                 : "=r"(r[0]), "=r"(r[1]), "=r"(r[2]), "=r"(r[3]) : "r"(addr));
}
__device__ __forceinline__ void mma_f16(float c[4], const uint32_t a[4],
                                        const uint32_t b0, const uint32_t b1) {
    asm volatile(
        "mma.sync.aligned.m16n8k16.row.col.f32.f16.f16.f32 "
        "{%0,%1,%2,%3}, {%4,%5,%6,%7}, {%8,%9}, {%0,%1,%2,%3};"
        : "+f"(c[0]), "+f"(c[1]), "+f"(c[2]), "+f"(c[3])
        : "r"(a[0]), "r"(a[1]), "r"(a[2]), "r"(a[3]), "r"(b0), "r"(b1));
}
#define CP_ASYNC16(dst, src) \
    asm volatile("cp.async.cg.shared.global [%0], [%1], 16;" :: "r"(dst), "l"(src))
#define CP_COMMIT() asm volatile("cp.async.commit_group;" ::: "memory")
#define CP_WAIT(n)  asm volatile("cp.async.wait_group %0;" :: "n"(n) : "memory")

// ---------- pre-kernel 1: reflect-extended fp16 signal (16B stores) ----------
__global__ void build_ext(const float* __restrict__ x) {
    const int row = blockIdx.x;
    const float* __restrict__ xr = x + (size_t)row * T_LEN;
    __half* __restrict__ er = g_ext + (size_t)row * EXT_STRIDE;
    const float x0 = xr[0], xl = xr[T_LEN - 1];
    for (int e0 = 8 * threadIdx.x; e0 < EXT_STRIDE; e0 += 8 * 256) {
        const int m0 = e0 - HALF;               // even
        __half v[8];
        if (m0 >= 0 && m0 + 8 <= T_LEN) {
#pragma unroll
            for (int u = 0; u < 4; ++u) {
                const float2 f = *reinterpret_cast<const float2*>(xr + m0 + 2 * u);
                v[2 * u]     = __float2half_rn(f.x);
                v[2 * u + 1] = __float2half_rn(f.y);
            }
        } else {
#pragma unroll
            for (int u = 0; u < 8; ++u) {
                const int m = m0 + u;
                float t;
                if (m < 0)           t = 2.0f * x0 - xr[-m];
                else if (m >= T_LEN) t = 2.0f * xl - xr[2 * T_LEN - 2 - m];
                else                 t = xr[m];
                v[u] = __float2half_rn(t);
            }
        }
        *reinterpret_cast<uint4*>(er + e0) = *reinterpret_cast<const uint4*>(v);
    }
}

// ---------- pre-kernel 2: Toeplitz strip ----------
__global__ void build_as(const float* __restrict__ hcoef) {
    for (int idx = threadIdx.x; idx < 16 * 448; idx += 256) {
        const int r  = idx / 448;
        const int kq = idx - r * 448;
        const int j  = kq - r;
        const float gv = (j >= 0 && j <= 412) ? hcoef[412 - j] : 0.0f;
        *reinterpret_cast<__half*>(g_As + r * AS_STRIDE + 2 * kq) = __float2half_rn(gv);
    }
}

// ---------- main kernel ----------
__global__ void __launch_bounds__(NTHREADS, 2)
fir_mma(float* __restrict__ out) {
    extern __shared__ char smem[];
    const uint32_t sb = smem_u32(smem);
    const int tid  = threadIdx.x;
    const int wid  = tid >> 5;           // 0..7 : rows [16*wid, 16*wid+16)
    const int lane = tid & 31;
    const int i0   = blockIdx.x;
    const int r0   = blockIdx.y * 128;

    // ---- copy Toeplitz strip to smem ----
    {
        const uint4* src = reinterpret_cast<const uint4*>(g_As);
        uint4* dst = reinterpret_cast<uint4*>(smem + OFF_AS);
        for (int i = tid; i < (16 * AS_STRIDE) / 16; i += NTHREADS) dst[i] = src[i];
    }

    // ---- producer: thread -> (row, 32-sample segment), pure cp.async ----
    const int prow = tid >> 1;
    const int pseg = tid & 1;
    const __half* psrc = g_ext + (size_t)(r0 + prow) * EXT_STRIDE
                         + i0 * 128 + pseg * 32;
    const uint32_t pdst = sb + (uint32_t)(prow * BS_STRIDE + pseg * 64);

    // ---- consumer ldmatrix addresses ----
    const uint32_t as_base = sb + OFF_AS +
        (uint32_t)((lane & 15) * AS_STRIDE + ((lane >> 4) & 1) * 16);
    // B x4 (2 n-blocks from this warp's 16 rows):
    // lanes 0-7: rows n0+(lane&7), +0 | 8-15: same rows, +16
    // lanes 16-23: rows n0+8+(lane&7), +0 | 24-31: +16
    const uint32_t b_off = (uint32_t)((16 * wid + 8 * ((lane >> 4) & 1) + (lane & 7)) * BS_STRIDE
                                      + 16 * ((lane >> 3) & 1));

    float acc[8][2][4];
#pragma unroll
    for (int e = 0; e < 8; ++e)
#pragma unroll
        for (int s = 0; s < 2; ++s)
#pragma unroll
            for (int q = 0; q < 4; ++q) acc[e][s][q] = 0.0f;

    uint32_t af[8][4];                   // A-fragment ring (diag kb in slot kb&7)

    // prologue: chunk 0 in flight
    {
        const uint32_t d = pdst + OFF_B0;
#pragma unroll
        for (int q = 0; q < 4; ++q) CP_ASYNC16(d + 16 * q, psrc + 8 * q);
        CP_COMMIT();
    }

#pragma unroll
    for (int c = 0; c < NCHUNK; ++c) {
        if (c + 1 < NCHUNK) {
            const __half* s = psrc + 64 * (c + 1);
            const uint32_t d = pdst + (((c + 1) & 1) ? OFF_B1 : OFF_B0);
#pragma unroll
            for (int q = 0; q < 4; ++q) CP_ASYNC16(d + 16 * q, s + 8 * q);
            CP_COMMIT();
            CP_WAIT(1);                  // chunk c complete (c+1 may be pending)
        } else {
            CP_WAIT(0);
        }
        __syncthreads();

        const uint32_t bbuf = sb + ((c & 1) ? OFF_B1 : OFF_B0) + b_off;

#pragma unroll
        for (int j = 0; j < 4; ++j) {
            const int kb = 4 * c + j;                      // compile-time
            if (kb <= DMAX)
                ldx4(af[kb & 7], as_base + (kb << 5));

            if (kb <= DMAX + 7) {                          // some e valid
                uint32_t bh[4];                            // nb0={0,1}, nb1={2,3}
                ldx4(bh, bbuf + (uint32_t)(32 * j));
#pragma unroll
                for (int e = 0; e < 8; ++e) {
                    if (kb - e >= 0 && kb - e <= DMAX) {
                        mma_f16(acc[e][0], af[(kb - e) & 7], bh[0], bh[1]);
                        mma_f16(acc[e][1], af[(kb - e) & 7], bh[2], bh[3]);
                    }
                }
            }
        }
        __syncthreads();
    }

    // ---- epilogue: single-pass smem transpose -> coalesced stores ----
    float* S = reinterpret_cast<float*>(smem);    // S[n][t], stride 136 floats
#pragma unroll
    for (int e = 0; e < 8; ++e)
#pragma unroll
        for (int s = 0; s < 2; ++s) {
            const int tl = 16 * e + (lane >> 2);
            const int nl = 16 * wid + 8 * s + 2 * (lane & 3);
            S[nl * 136 + tl]           = acc[e][s][0];
            S[(nl + 1) * 136 + tl]     = acc[e][s][1];
            S[nl * 136 + tl + 8]       = acc[e][s][2];
            S[(nl + 1) * 136 + tl + 8] = acc[e][s][3];
        }
    __syncthreads();

    const int tg = i0 * 128 + 4 * lane;
    if (tg < T_LEN) {
#pragma unroll
        for (int rr = 0; rr < 16; ++rr) {
            const int n = wid * 16 + rr;
            const float4 v = *reinterpret_cast<const float4*>(&S[n * 136 + 4 * lane]);
            *reinterpret_cast<float4*>(&out[(size_t)(r0 + n) * T_LEN + tg]) = v;
        }
    }
}

extern "C" void kernel_launch(void* const* d_in, const int* in_sizes, int n_in,
                              void* d_out, int out_size) {
    const float* x = (const float*)d_in[0];   // (32, 64, 30000) f32
    const float* h = (const float*)d_in[1];   // (413,) f32
    float* out = (float*)d_out;

    cudaFuncSetAttribute(fir_mma,
                         cudaFuncAttributeMaxDynamicSharedMemorySize, SMEM_REQ);

    build_ext<<<NROWS, 256>>>(x);
    build_as<<<1, 256>>>(h);

    dim3 grid(NT_I0, NROWS / 128);
    fir_mma<<<grid, NTHREADS, SMEM_REQ>>>(out);
}

// round 15
// speedup vs baseline: 1.6003x; 1.1362x over previous
#include <cuda_runtime.h>
#include <cuda_fp16.h>
#include <cstdint>

// FIR bandpass as banded-Toeplitz GEMM on mma.sync — fp16, 8-deep-M warps.
// R15: B tiles are WARP-PRIVATE (producer rows == consumer rows per warp):
//      block barriers in the mainloop replaced by cp.async.wait_group + syncwarp,
//      3-stage cp.async pipeline, warp-local epilogue sync.
//
// out[t] = sum_j g[j] * xv[t-206+j],  g[j] = h[412-j]
// D[i,n] = sum_k A[i,k] * B[n,k],  A[i,k] = g[k-i]  (banded: 0 <= k-i <= 412)

#define T_LEN    30000
#define NROWS    2048
#define HALF     206
#define NCHUNK   9             // chunks of 64 samples (kb = 0..35; kb>33 folds away)
#define DMAX     26
#define NTHREADS 256
#define NT_I0    235           // ceil(30000/128)
#define EXT_STRIDE 30720       // halves per row (30412 used, padded, 16B-aligned)

#define AS_STRIDE 912          // 448 fp16 + 16B pad  (228 words ≡ 4 mod 32)
#define BS_STRIDE 144          // 64 fp16 + 16B pad   (36 words ≡ 4 mod 32)
#define OFF_AS   0             // 16 * 912 = 14592
#define OFF_B0   14592         // 3 buffers x 128*144 = 18432 each
#define OFF_B1   33024
#define OFF_B2   51456
#define SMEM_REQ 69888         // max(69888, epilogue staging 69632)

// reflect-extended fp16 signal: ext[row][e] = xv[row][e - 206]
__device__ __align__(16) __half g_ext[(size_t)NROWS * EXT_STRIDE];
__device__ __align__(16) char g_As[16 * AS_STRIDE];

__device__ __forceinline__ uint32_t smem_u32(const void* p) {
    return (uint32_t)__cvta_generic_to_shared(p);
}
__device__ __forceinline__ void ldx4(uint32_t r[4], uint32_t addr) {
    asm volatile("ldmatrix.sync.aligned.m8n8.x4.shared.b16 {%0,%1,%2,%3}, [%4];"
                 : "=r"(r[0]), "=r"(r[1]), "=r"(r[2]), "=r"(r[3]) : "r"(addr));
}
__device__ __forceinline__ void mma_f16(float c[4], const uint32_t a[4],
                                        const uint32_t b0, const uint32_t b1) {
    asm volatile(
        "mma.sync.aligned.m16n8k16.row.col.f32.f16.f16.f32 "
        "{%0,%1,%2,%3}, {%4,%5,%6,%7}, {%8,%9}, {%0,%1,%2,%3};"
        : "+f"(c[0]), "+f"(c[1]), "+f"(c[2]), "+f"(c[3])
        : "r"(a[0]), "r"(a[1]), "r"(a[2]), "r"(a[3]), "r"(b0), "r"(b1));
}
#define CP_ASYNC16(dst, src) \
    asm volatile("cp.async.cg.shared.global [%0], [%1], 16;" :: "r"(dst), "l"(src))
#define CP_COMMIT() asm volatile("cp.async.commit_group;" ::: "memory")
#define CP_WAIT(n)  asm volatile("cp.async.wait_group %0;" :: "n"(n) : "memory")

// ---------- pre-kernel 1: reflect-extended fp16 signal (16B stores) ----------
__global__ void build_ext(const float* __restrict__ x) {
    const int row = blockIdx.x;
    const float* __restrict__ xr = x + (size_t)row * T_LEN;
    __half* __restrict__ er = g_ext + (size_t)row * EXT_STRIDE;
    const float x0 = xr[0], xl = xr[T_LEN - 1];
    for (int e0 = 8 * threadIdx.x; e0 < EXT_STRIDE; e0 += 8 * 256) {
        const int m0 = e0 - HALF;               // even
        __half v[8];
        if (m0 >= 0 && m0 + 8 <= T_LEN) {
#pragma unroll
            for (int u = 0; u < 4; ++u) {
                const float2 f = *reinterpret_cast<const float2*>(xr + m0 + 2 * u);
                v[2 * u]     = __float2half_rn(f.x);
                v[2 * u + 1] = __float2half_rn(f.y);
            }
        } else {
#pragma unroll
            for (int u = 0; u < 8; ++u) {
                const int m = m0 + u;
                float t;
                if (m < 0)           t = 2.0f * x0 - xr[-m];
                else if (m >= T_LEN) t = 2.0f * xl - xr[2 * T_LEN - 2 - m];
                else                 t = xr[m];
                v[u] = __float2half_rn(t);
            }
        }
        *reinterpret_cast<uint4*>(er + e0) = *reinterpret_cast<const uint4*>(v);
    }
}

// ---------- pre-kernel 2: Toeplitz strip ----------
__global__ void build_as(const float* __restrict__ hcoef) {
    for (int idx = threadIdx.x; idx < 16 * 448; idx += 256) {
        const int r  = idx / 448;
        const int kq = idx - r * 448;
        const int j  = kq - r;
        const float gv = (j >= 0 && j <= 412) ? hcoef[412 - j] : 0.0f;
        *reinterpret_cast<__half*>(g_As + r * AS_STRIDE + 2 * kq) = __float2half_rn(gv);
    }
}

// ---------- main kernel ----------
__global__ void __launch_bounds__(NTHREADS, 2)
fir_mma(float* __restrict__ out) {
    extern __shared__ char smem[];
    const uint32_t sb = smem_u32(smem);
    const int tid  = threadIdx.x;
    const int wid  = tid >> 5;           // 0..7 : rows [16*wid, 16*wid+16)
    const int lane = tid & 31;
    const int i0   = blockIdx.x;
    const int r0   = blockIdx.y * 128;

    // ---- copy Toeplitz strip to smem (block-wide, needs one barrier) ----
    {
        const uint4* src = reinterpret_cast<const uint4*>(g_As);
        uint4* dst = reinterpret_cast<uint4*>(smem + OFF_AS);
        for (int i = tid; i < (16 * AS_STRIDE) / 16; i += NTHREADS) dst[i] = src[i];
    }

    // ---- producer: thread -> (row tid>>1, 32-sample segment) — WARP-PRIVATE ----
    const int prow = tid >> 1;           // rows 16*wid .. 16*wid+15 for this warp
    const int pseg = tid & 1;
    const __half* psrc = g_ext + (size_t)(r0 + prow) * EXT_STRIDE
                         + i0 * 128 + pseg * 32;
    const uint32_t pdst = sb + (uint32_t)(prow * BS_STRIDE + pseg * 64);

    // ---- consumer ldmatrix addresses (reads only this warp's 16 rows) ----
    const uint32_t as_base = sb + OFF_AS +
        (uint32_t)((lane & 15) * AS_STRIDE + ((lane >> 4) & 1) * 16);
    const uint32_t b_off = (uint32_t)((16 * wid + 8 * ((lane >> 4) & 1) + (lane & 7)) * BS_STRIDE
                                      + 16 * ((lane >> 3) & 1));

    float acc[8][2][4];
#pragma unroll
    for (int e = 0; e < 8; ++e)
#pragma unroll
        for (int s = 0; s < 2; ++s)
#pragma unroll
            for (int q = 0; q < 4; ++q) acc[e][s][q] = 0.0f;

    uint32_t af[8][4];                   // A-fragment ring (diag kb in slot kb&7)

    // prologue: chunks 0 and 1 in flight (3-stage pipeline)
    {
        const uint32_t d0 = pdst + OFF_B0;
#pragma unroll
        for (int q = 0; q < 4; ++q) CP_ASYNC16(d0 + 16 * q, psrc + 8 * q);
        CP_COMMIT();
        const uint32_t d1 = pdst + OFF_B1;
#pragma unroll
        for (int q = 0; q < 4; ++q) CP_ASYNC16(d1 + 16 * q, psrc + 64 + 8 * q);
        CP_COMMIT();
    }
    __syncthreads();                     // A strip visible to all warps

#pragma unroll
    for (int c = 0; c < NCHUNK; ++c) {
        if (c + 2 < NCHUNK) {
            const __half* s = psrc + 64 * (c + 2);
            const uint32_t boffs = ((c + 2) % 3 == 0) ? OFF_B0
                                 : ((c + 2) % 3 == 1) ? OFF_B1 : OFF_B2;
            const uint32_t d = pdst + boffs;
#pragma unroll
            for (int q = 0; q < 4; ++q) CP_ASYNC16(d + 16 * q, s + 8 * q);
            CP_COMMIT();
            CP_WAIT(2);                  // chunk c complete (c+1, c+2 pending)
        } else if (c + 1 < NCHUNK) {
            CP_WAIT(1);                  // chunk c complete (c+1 pending)
        } else {
            CP_WAIT(0);
        }
        __syncwarp();                    // warp-local visibility of B tile

        const uint32_t bbuf = sb + ((c % 3 == 0) ? OFF_B0
                                   : (c % 3 == 1) ? OFF_B1 : OFF_B2) + b_off;

#pragma unroll
        for (int j = 0; j < 4; ++j) {
            const int kb = 4 * c + j;                      // compile-time
            if (kb <= DMAX)
                ldx4(af[kb & 7], as_base + (kb << 5));

            if (kb <= DMAX + 7) {                          // some e valid
                uint32_t bh[4];                            // nb0={0,1}, nb1={2,3}
                ldx4(bh, bbuf + (uint32_t)(32 * j));
#pragma unroll
                for (int e = 0; e < 8; ++e) {
                    if (kb - e >= 0 && kb - e <= DMAX) {
                        mma_f16(acc[e][0], af[(kb - e) & 7], bh[0], bh[1]);
                        mma_f16(acc[e][1], af[(kb - e) & 7], bh[2], bh[3]);
                    }
                }
            }
        }
        // no block barrier: B buffers are warp-private
    }

    __syncthreads();                     // all warps done reading A strip / B bufs
                                         // before smem is reused as staging

    // ---- epilogue: staging rows are warp-private too ----
    float* S = reinterpret_cast<float*>(smem);    // S[n][t], stride 136 floats
#pragma unroll
    for (int e = 0; e < 8; ++e)
#pragma unroll
        for (int s = 0; s < 2; ++s) {
            const int tl = 16 * e + (lane >> 2);
            const int nl = 16 * wid + 8 * s + 2 * (lane & 3);
            S[nl * 136 + tl]           = acc[e][s][0];
            S[(nl + 1) * 136 + tl]     = acc[e][s][1];
            S[nl * 136 + tl + 8]       = acc[e][s][2];
            S[(nl + 1) * 136 + tl + 8] = acc[e][s][3];
        }
    __syncwarp();                        // warp wrote rows 16*wid..+15, reads same

    const int tg = i0 * 128 + 4 * lane;
    if (tg < T_LEN) {
#pragma unroll
        for (int rr = 0; rr < 16; ++rr) {
            const int n = wid * 16 + rr;
            const float4 v = *reinterpret_cast<const float4*>(&S[n * 136 + 4 * lane]);
            *reinterpret_cast<float4*>(&out[(size_t)(r0 + n) * T_LEN + tg]) = v;
        }
    }
}

extern "C" void kernel_launch(void* const* d_in, const int* in_sizes, int n_in,
                              void* d_out, int out_size) {
    const float* x = (const float*)d_in[0];   // (32, 64, 30000) f32
    const float* h = (const float*)d_in[1];   // (413,) f32
    float* out = (float*)d_out;

    cudaFuncSetAttribute(fir_mma,
                         cudaFuncAttributeMaxDynamicSharedMemorySize, SMEM_REQ);

    build_ext<<<NROWS, 256>>>(x);
    build_as<<<1, 256>>>(h);

    dim3 grid(NT_I0, NROWS / 128);
    fir_mma<<<grid, NTHREADS, SMEM_REQ>>>(out);
}